// round 3
// baseline (speedup 1.0000x reference)
#include <cuda_runtime.h>
#include <cstddef>

#define NPTS 50000
#define C    96
#define G    6
#define S    16

typedef unsigned long long u64;

// packed fp32x2 helpers -------------------------------------------------------
__device__ __forceinline__ u64 fma2(u64 a, u64 b, u64 c) {
    u64 d;
    asm("fma.rn.f32x2 %0, %1, %2, %3;" : "=l"(d) : "l"(a), "l"(b), "l"(c));
    return d;
}
__device__ __forceinline__ float lo2(u64 v) { return __uint_as_float((unsigned)v); }
__device__ __forceinline__ float hi2(u64 v) { return __uint_as_float((unsigned)(v >> 32)); }
__device__ __forceinline__ float hsum2(u64 v) { return lo2(v) + hi2(v); }
__device__ __forceinline__ u64 dup2(float x) {
    u64 r;
    asm("mov.b64 %0, {%1, %1};" : "=l"(r) : "r"(__float_as_uint(x)));
    return r;
}

// ---------------- scratch (static device globals) ----------------------------
__device__ float d_v   [NPTS * C];
__device__ float d_qW  [NPTS * G];
__device__ float d_kW  [NPTS * G];
__device__ float d_MT  [G * C];      // MT[g][cc] = (Wp2 @ Ww1)[cc][g]
__device__ float d_bM  [G];          // bp2 @ Ww1
__device__ float d_Wp2T[C * C];      // [co][ci]

// ---------------- k1: QKV projections + qW/kW + fused precompute -------------
#define K1_TILE 128
#define K1_THREADS 512
#define K1_SMEM_F (K1_TILE*100 + C*100 + K1_TILE*100 + G*100)
#define K1_SMEM (K1_SMEM_F * 4)

__global__ __launch_bounds__(K1_THREADS)
void k1_qkv(const float* __restrict__ feat,
            const float* __restrict__ Wq, const float* __restrict__ bq,
            const float* __restrict__ gq, const float* __restrict__ betaq,
            const float* __restrict__ Wk, const float* __restrict__ bk,
            const float* __restrict__ gk, const float* __restrict__ betak,
            const float* __restrict__ Wv, const float* __restrict__ bv,
            const float* __restrict__ Ww1,
            const float* __restrict__ Wp2, const float* __restrict__ bp2)
{
    const int tid = threadIdx.x;

    // ---- fused precompute block ----
    if (blockIdx.x == gridDim.x - 1) {
        for (int i = tid; i < C * C; i += K1_THREADS) {
            int co = i / C, ci = i % C;
            d_Wp2T[i] = __ldg(&Wp2[ci * C + co]);
        }
        for (int i = tid; i < G * C; i += K1_THREADS) {
            int g = i / C, cc = i % C;
            float s = 0.f;
            #pragma unroll 4
            for (int c2 = 0; c2 < C; c2++)
                s = fmaf(__ldg(&Wp2[cc * C + c2]), __ldg(&Ww1[c2 * G + g]), s);
            d_MT[i] = s;
        }
        if (tid < G) {
            float s = 0.f;
            for (int c2 = 0; c2 < C; c2++)
                s = fmaf(__ldg(&bp2[c2]), __ldg(&Ww1[c2 * G + tid]), s);
            d_bM[tid] = s;
        }
        return;
    }

    extern __shared__ float sh[];
    float* featS = sh;                        // [p][k] stride 100
    float* WST   = sh + K1_TILE * 100;        // [c][k] stride 100
    float* tmpS  = WST + C * 100;             // [p][c] stride 100
    float* Ww1T  = tmpS + K1_TILE * 100;      // [g][c] stride 100

    const int n0 = blockIdx.x * K1_TILE;
    const float RS = rsqrtf(1.0f + 1e-5f);

    for (int i = tid; i < K1_TILE * 24; i += K1_THREADS) {
        int p = i / 24, kq = (i % 24) * 4;
        int n = n0 + p;
        float4 vv = (n < NPTS) ? *(const float4*)&feat[(size_t)n * C + kq]
                               : make_float4(0.f, 0.f, 0.f, 0.f);
        *(float4*)&featS[p * 100 + kq] = vv;
    }
    for (int i = tid; i < C * G; i += K1_THREADS) {
        int c2 = i / G, g = i % G;
        Ww1T[g * 100 + c2] = Ww1[i];
    }

    const int tx = tid & 31, ty = tid >> 5;   // ty 0..15, 8 points each

    for (int m = 0; m < 3; m++) {
        __syncthreads();
        const float* W = (m == 0) ? Wq : (m == 1) ? Wk : Wv;
        for (int i = tid; i < C * 24; i += K1_THREADS) {
            int k = i / 24, cq = (i % 24) * 4;
            float4 w = *(const float4*)&W[k * C + cq];
            WST[(cq + 0) * 100 + k] = w.x;
            WST[(cq + 1) * 100 + k] = w.y;
            WST[(cq + 2) * 100 + k] = w.z;
            WST[(cq + 3) * 100 + k] = w.w;
        }
        __syncthreads();

        u64 acc[8][3];
        #pragma unroll
        for (int pp = 0; pp < 8; pp++)
            acc[pp][0] = acc[pp][1] = acc[pp][2] = 0ull;

        #pragma unroll 2
        for (int k4 = 0; k4 < C; k4 += 4) {
            ulonglong2 b0 = *(const ulonglong2*)&WST[tx * 100 + k4];
            ulonglong2 b1 = *(const ulonglong2*)&WST[(tx + 32) * 100 + k4];
            ulonglong2 b2 = *(const ulonglong2*)&WST[(tx + 64) * 100 + k4];
            #pragma unroll
            for (int pp = 0; pp < 8; pp++) {
                ulonglong2 a = *(const ulonglong2*)&featS[(ty * 8 + pp) * 100 + k4];
                acc[pp][0] = fma2(a.x, b0.x, acc[pp][0]);
                acc[pp][0] = fma2(a.y, b0.y, acc[pp][0]);
                acc[pp][1] = fma2(a.x, b1.x, acc[pp][1]);
                acc[pp][1] = fma2(a.y, b1.y, acc[pp][1]);
                acc[pp][2] = fma2(a.x, b2.x, acc[pp][2]);
                acc[pp][2] = fma2(a.y, b2.y, acc[pp][2]);
            }
        }

        if (m < 2) {
            const float* bb_ = (m == 0) ? bq : bk;
            const float* gg_ = (m == 0) ? gq : gk;
            const float* bt_ = (m == 0) ? betaq : betak;
            float bb[3], sc[3], bt[3];
            #pragma unroll
            for (int cc = 0; cc < 3; cc++) {
                int ch = tx + 32 * cc;
                bb[cc] = bb_[ch];
                sc[cc] = gg_[ch] * RS;
                bt[cc] = bt_[ch];
            }
            #pragma unroll
            for (int pp = 0; pp < 8; pp++) {
                int p = ty * 8 + pp;
                #pragma unroll
                for (int cc = 0; cc < 3; cc++) {
                    float r = hsum2(acc[pp][cc]);
                    float v = fmaf(r + bb[cc], sc[cc], bt[cc]);
                    tmpS[p * 100 + tx + 32 * cc] = fmaxf(v, 0.f);
                }
            }
            __syncthreads();
            float* dst = (m == 0) ? d_qW : d_kW;
            for (int t = tid; t < K1_TILE * G; t += K1_THREADS) {
                int p = t / G, g = t % G;
                int n = n0 + p;
                if (n < NPTS) {
                    u64 s2 = 0ull;
                    #pragma unroll
                    for (int c4 = 0; c4 < C; c4 += 4) {
                        ulonglong2 hv = *(const ulonglong2*)&tmpS[p * 100 + c4];
                        ulonglong2 wv = *(const ulonglong2*)&Ww1T[g * 100 + c4];
                        s2 = fma2(hv.x, wv.x, s2);
                        s2 = fma2(hv.y, wv.y, s2);
                    }
                    dst[(size_t)n * G + g] = hsum2(s2);
                }
            }
        } else {
            float bb[3];
            #pragma unroll
            for (int cc = 0; cc < 3; cc++) bb[cc] = bv[tx + 32 * cc];
            #pragma unroll
            for (int pp = 0; pp < 8; pp++) {
                int p = ty * 8 + pp;
                #pragma unroll
                for (int cc = 0; cc < 3; cc++)
                    tmpS[p * 100 + tx + 32 * cc] = hsum2(acc[pp][cc]) + bb[cc];
            }
            __syncthreads();
            for (int i = tid; i < K1_TILE * 24; i += K1_THREADS) {
                int p = i / 24, cq = (i % 24) * 4;
                int n = n0 + p;
                if (n < NPTS)
                    *(float4*)&d_v[(size_t)n * C + cq] = *(const float4*)&tmpS[p * 100 + cq];
            }
        }
    }
}

// ---------------- k2: per-point attention ------------------------------------
#define PTS 5
#define K2_THREADS (PTS * C)      // 480
#define POD_F 2608
#define K2_SMEM_F (C*100 + G*100 + 68 + PTS*POD_F)   // 23308 floats = 93.2KB
#define K2_SMEM (K2_SMEM_F * 4)

__device__ __forceinline__ void podbar(int pod) {
    asm volatile("bar.sync %0, 96;" :: "r"(pod + 1) : "memory");
}

__global__ __launch_bounds__(K2_THREADS, 2)
void k2_attn(const float* __restrict__ coord,
             const int*   __restrict__ refidx,
             const float* __restrict__ Wp1, const float* __restrict__ bp1,
             const float* __restrict__ gp,  const float* __restrict__ betap,
             const float* __restrict__ bp2,
             const float* __restrict__ bw1, const float* __restrict__ gw,
             const float* __restrict__ betaw,
             const float* __restrict__ Ww2, const float* __restrict__ bw2,
             float* __restrict__ out)
{
    extern __shared__ float sh[];
    float* Wp2T = sh;                  // [co][ci] stride 100
    float* MTs  = sh + C * 100;        // [g][cc] stride 100
    float* cst  = MTs + G * 100;       // Ww2(36) bw2(6) bw1(6) gw(6) betaw(6) bM(6)
    float* podb = cst + 68;

    const int tid = threadIdx.x;
    const int pod = tid / C;
    const int c   = tid % C;
    const int n   = blockIdx.x * PTS + pod;   // 50000 = 10000*5

    float* P    = podb + pod * POD_F;
    float* hs   = P;            // [16][100]
    float* Hs   = P + 1600;     // [6][100]
    float* ws   = P + 2200;     // [16][8]
    float* us   = P + 2328;     // [16][6]
    float* wls  = P + 2424;     // [16][6]
    float* pos  = P + 2520;     // [16][4]
    float* wsum = P + 2584;     // [8]
    int*   js   = (int*)(P + 2592);  // [16]

    const float RS = rsqrtf(1.0f + 1e-5f);

    // ---- staging ----
    for (int i = tid; i < C * 24; i += K2_THREADS) {
        int co = i / 24, ciq = (i % 24) * 4;
        *(float4*)&Wp2T[co * 100 + ciq] = *(const float4*)&d_Wp2T[co * C + ciq];
    }
    for (int i = tid; i < G * C; i += K2_THREADS)
        MTs[(i / C) * 100 + (i % C)] = d_MT[i];
    if      (tid < 36) cst[tid] = Ww2[tid];
    else if (tid < 42) cst[tid] = bw2[tid - 36];
    else if (tid < 48) cst[tid] = bw1[tid - 42];
    else if (tid < 54) cst[tid] = gw[tid - 48];
    else if (tid < 60) cst[tid] = betaw[tid - 54];
    else if (tid < 66) cst[tid] = d_bM[tid - 60];

    // P1/P2: indices + relative positions
    if (c < S) js[c] = refidx[(size_t)n * S + c];
    if (c < 48) {
        int s = c / 3, d = c % 3;
        int j = __ldg(&refidx[(size_t)n * S + s]);
        pos[s * 4 + d] = __ldg(&coord[(size_t)j * 3 + d]) - __ldg(&coord[(size_t)n * 3 + d]);
    } else if (c < 64) {
        pos[(c - 48) * 4 + 3] = 0.f;
    }
    __syncthreads();

    // P3: h[s][c] = relu(bn(pos@Wp1 + bp1))
    float w10 = __ldg(&Wp1[c]);
    float w11 = __ldg(&Wp1[C + c]);
    float w12 = __ldg(&Wp1[2 * C + c]);
    float bp1c = __ldg(&bp1[c]);
    float sp   = __ldg(&gp[c]) * RS;
    float btp  = __ldg(&betap[c]);
    #pragma unroll
    for (int s = 0; s < 16; s++) {
        float4 p4 = *(const float4*)&pos[s * 4];
        float hv = fmaf(p4.x, w10, fmaf(p4.y, w11, fmaf(p4.z, w12, bp1c)));
        hs[s * 100 + c] = fmaxf(fmaf(hv, sp, btp), 0.0f);
    }
    podbar(pod);

    // P4: u[s][g] = relu(bn(kW[j]-qW[n] + h@M + bM + bw1))
    {
        int s = c / 6, g = c % 6;
        u64 a2 = 0ull;
        #pragma unroll
        for (int c4 = 0; c4 < C; c4 += 4) {
            ulonglong2 hv = *(const ulonglong2*)&hs[s * 100 + c4];
            ulonglong2 mv = *(const ulonglong2*)&MTs[g * 100 + c4];
            a2 = fma2(hv.x, mv.x, a2);
            a2 = fma2(hv.y, mv.y, a2);
        }
        float kq = __ldg(&d_kW[(size_t)js[s] * G + g]) - __ldg(&d_qW[(size_t)n * G + g]);
        float t = kq + hsum2(a2) + cst[60 + g] + cst[42 + g];
        us[s * 6 + g] = fmaxf(fmaf(t, cst[48 + g] * RS, cst[54 + g]), 0.0f);
    }
    podbar(pod);

    // P5: logits = u @ Ww2 + bw2
    {
        int s = c / 6, g2 = c % 6;
        float lg = cst[36 + g2];
        #pragma unroll
        for (int g = 0; g < 6; g++) lg = fmaf(us[s * 6 + g], cst[g * 6 + g2], lg);
        wls[s * 6 + g2] = lg;
    }
    podbar(pod);

    // P6: softmax over s per g (6 threads/pod)
    if (c < 6) {
        int g = c;
        float m = -1e30f;
        #pragma unroll
        for (int s = 0; s < 16; s++) m = fmaxf(m, wls[s * 6 + g]);
        float sum = 0.f;
        #pragma unroll
        for (int s = 0; s < 16; s++) sum += __expf(wls[s * 6 + g] - m);
        float inv = 1.0f / sum;
        float accw = 0.f;
        #pragma unroll
        for (int s = 0; s < 16; s++) {
            int jp1 = js[s] + 1;
            float msk = (float)((jp1 > 0) - (jp1 < 0));
            float w = __expf(wls[s * 6 + g] - m) * inv * msk;
            ws[s * 8 + g] = w;
            accw += w;
        }
        wsum[g] = accw;
    }
    podbar(pod);

    // P7: H[g][c] = sum_s w[s][g]*h[s][c]; vsum = sum_s w[s][gc]*v[j_s][c]
    int gc = c >> 4;
    u64 Hg2[3] = {0ull, 0ull, 0ull};
    float vsum = 0.f;
    #pragma unroll
    for (int s = 0; s < 16; s++) {
        ulonglong2 w01 = *(const ulonglong2*)&ws[s * 8];   // g0..g3
        u64 w2 = *(const u64*)&ws[s * 8 + 4];              // g4,g5
        float h = hs[s * 100 + c];
        u64 hh = dup2(h);
        Hg2[0] = fma2(hh, w01.x, Hg2[0]);
        Hg2[1] = fma2(hh, w01.y, Hg2[1]);
        Hg2[2] = fma2(hh, w2,    Hg2[2]);
        float wg = ws[s * 8 + gc];
        vsum = fmaf(wg, __ldg(&d_v[(size_t)js[s] * C + c]), vsum);
    }
    Hs[0 * 100 + c] = lo2(Hg2[0]);
    Hs[1 * 100 + c] = hi2(Hg2[0]);
    Hs[2 * 100 + c] = lo2(Hg2[1]);
    Hs[3 * 100 + c] = hi2(Hg2[1]);
    Hs[4 * 100 + c] = lo2(Hg2[2]);
    Hs[5 * 100 + c] = hi2(Hg2[2]);
    podbar(pod);

    // P8: out[c] = vsum + bp2[c]*wsum[gc] + H[gc] . Wp2[:,c]
    float accs = fmaf(__ldg(&bp2[c]), wsum[gc], vsum);
    u64 a2 = 0ull;
    #pragma unroll
    for (int c4 = 0; c4 < C; c4 += 4) {
        ulonglong2 hh = *(const ulonglong2*)&Hs[gc * 100 + c4];
        ulonglong2 wv = *(const ulonglong2*)&Wp2T[c * 100 + c4];
        a2 = fma2(hh.x, wv.x, a2);
        a2 = fma2(hh.y, wv.y, a2);
    }
    out[(size_t)n * C + c] = accs + hsum2(a2);
}

// ---------------- host launcher ---------------------------------------------
extern "C" void kernel_launch(void* const* d_in, const int* in_sizes, int n_in,
                              void* d_out, int out_size)
{
    bool dict = (in_sizes[2] == NPTS * S);

    const float* feat  = (const float*)d_in[0];
    const float* coord = (const float*)d_in[1];
    const int*   ref   = (const int*)d_in[dict ? 2 : 24];
    int wb = dict ? 3 : 2;
    const float* Wq    = (const float*)d_in[wb + 0];
    const float* bq    = (const float*)d_in[wb + 1];
    const float* gq    = (const float*)d_in[wb + 2];
    const float* betaq = (const float*)d_in[wb + 3];
    const float* Wk    = (const float*)d_in[wb + 4];
    const float* bk    = (const float*)d_in[wb + 5];
    const float* gk    = (const float*)d_in[wb + 6];
    const float* betak = (const float*)d_in[wb + 7];
    const float* Wv    = (const float*)d_in[wb + 8];
    const float* bv    = (const float*)d_in[wb + 9];
    const float* Wp1   = (const float*)d_in[wb + 10];
    const float* bp1   = (const float*)d_in[wb + 11];
    const float* gp    = (const float*)d_in[wb + 12];
    const float* betap = (const float*)d_in[wb + 13];
    const float* Wp2   = (const float*)d_in[wb + 14];
    const float* bp2   = (const float*)d_in[wb + 15];
    const float* Ww1   = (const float*)d_in[wb + 16];
    const float* bw1   = (const float*)d_in[wb + 17];
    const float* gw    = (const float*)d_in[wb + 18];
    const float* betaw = (const float*)d_in[wb + 19];
    const float* Ww2   = (const float*)d_in[wb + 20];
    const float* bw2   = (const float*)d_in[wb + 21];
    float* out = (float*)d_out;

    cudaFuncSetAttribute(k1_qkv,  cudaFuncAttributeMaxDynamicSharedMemorySize, K1_SMEM);
    cudaFuncSetAttribute(k2_attn, cudaFuncAttributeMaxDynamicSharedMemorySize, K2_SMEM);

    int k1_blocks = (NPTS + K1_TILE - 1) / K1_TILE + 1;
    k1_qkv<<<k1_blocks, K1_THREADS, K1_SMEM>>>(
        feat, Wq, bq, gq, betaq, Wk, bk, gk, betak, Wv, bv, Ww1, Wp2, bp2);
    k2_attn<<<NPTS / PTS, K2_THREADS, K2_SMEM>>>(
        coord, ref, Wp1, bp1, gp, betap, bp2, bw1, gw, betaw, Ww2, bw2, out);
}

// round 4
// speedup vs baseline: 1.2988x; 1.2988x over previous
#include <cuda_runtime.h>
#include <cstddef>

#define NPTS 50000
#define C    96
#define G    6
#define S    16

typedef unsigned long long u64;

// packed fp32x2 helpers -------------------------------------------------------
__device__ __forceinline__ u64 fma2(u64 a, u64 b, u64 c) {
    u64 d;
    asm("fma.rn.f32x2 %0, %1, %2, %3;" : "=l"(d) : "l"(a), "l"(b), "l"(c));
    return d;
}
__device__ __forceinline__ float lo2(u64 v) { return __uint_as_float((unsigned)v); }
__device__ __forceinline__ float hi2(u64 v) { return __uint_as_float((unsigned)(v >> 32)); }
__device__ __forceinline__ float hsum2(u64 v) { return lo2(v) + hi2(v); }

// ---------------- scratch (static device globals) ----------------------------
__device__ float d_v   [NPTS * C];
__device__ float d_qW  [NPTS * G];
__device__ float d_kW  [NPTS * G];
__device__ float d_MT  [G * C];      // MT[g][cc] = (Wp2 @ Ww1)[cc][g]
__device__ float d_bM  [G];          // bp2 @ Ww1
__device__ float d_Wp2T[C * C];      // [co][ci]

// ---------------- k1: QKV projections + qW/kW + fused precompute -------------
#define K1_TILE 64
#define K1_THREADS 256
#define K1_SMEM_F (K1_TILE*100 + C*100 + K1_TILE*100 + G*100)   // 23000 = 92KB
#define K1_SMEM (K1_SMEM_F * 4)

__global__ __launch_bounds__(K1_THREADS, 2)
void k1_qkv(const float* __restrict__ feat,
            const float* __restrict__ Wq, const float* __restrict__ bq,
            const float* __restrict__ gq, const float* __restrict__ betaq,
            const float* __restrict__ Wk, const float* __restrict__ bk,
            const float* __restrict__ gk, const float* __restrict__ betak,
            const float* __restrict__ Wv, const float* __restrict__ bv,
            const float* __restrict__ Ww1,
            const float* __restrict__ Wp2, const float* __restrict__ bp2)
{
    const int tid = threadIdx.x;

    // ---- fused precompute block ----
    if (blockIdx.x == gridDim.x - 1) {
        for (int i = tid; i < C * C; i += K1_THREADS) {
            int co = i / C, ci = i % C;
            d_Wp2T[i] = __ldg(&Wp2[ci * C + co]);
        }
        for (int i = tid; i < G * C; i += K1_THREADS) {
            int g = i / C, cc = i % C;
            float s = 0.f;
            #pragma unroll 4
            for (int c2 = 0; c2 < C; c2++)
                s = fmaf(__ldg(&Wp2[cc * C + c2]), __ldg(&Ww1[c2 * G + g]), s);
            d_MT[i] = s;
        }
        if (tid < G) {
            float s = 0.f;
            for (int c2 = 0; c2 < C; c2++)
                s = fmaf(__ldg(&bp2[c2]), __ldg(&Ww1[c2 * G + tid]), s);
            d_bM[tid] = s;
        }
        return;
    }

    extern __shared__ float sh[];
    float* featS = sh;                        // [p][k] stride 100
    float* WST   = sh + K1_TILE * 100;        // [c][k] stride 100
    float* tmpS  = WST + C * 100;             // [p][c] stride 100
    float* Ww1T  = tmpS + K1_TILE * 100;      // [g][c] stride 100

    const int n0 = blockIdx.x * K1_TILE;
    const float RS = rsqrtf(1.0f + 1e-5f);

    for (int i = tid; i < K1_TILE * 24; i += K1_THREADS) {
        int p = i / 24, kq = (i % 24) * 4;
        int n = n0 + p;
        float4 vv = (n < NPTS) ? *(const float4*)&feat[(size_t)n * C + kq]
                               : make_float4(0.f, 0.f, 0.f, 0.f);
        *(float4*)&featS[p * 100 + kq] = vv;
    }
    for (int i = tid; i < C * G; i += K1_THREADS) {
        int c2 = i / G, g = i % G;
        Ww1T[g * 100 + c2] = Ww1[i];
    }

    const int tx = tid & 31, ty = tid >> 5;   // ty 0..7, 8 points each

    for (int m = 0; m < 3; m++) {
        __syncthreads();
        const float* W = (m == 0) ? Wq : (m == 1) ? Wk : Wv;
        for (int i = tid; i < C * 24; i += K1_THREADS) {
            int k = i / 24, cq = (i % 24) * 4;
            float4 w = *(const float4*)&W[k * C + cq];
            WST[(cq + 0) * 100 + k] = w.x;
            WST[(cq + 1) * 100 + k] = w.y;
            WST[(cq + 2) * 100 + k] = w.z;
            WST[(cq + 3) * 100 + k] = w.w;
        }
        __syncthreads();

        u64 acc[8][3];
        #pragma unroll
        for (int pp = 0; pp < 8; pp++)
            acc[pp][0] = acc[pp][1] = acc[pp][2] = 0ull;

        #pragma unroll 2
        for (int k4 = 0; k4 < C; k4 += 4) {
            ulonglong2 b0 = *(const ulonglong2*)&WST[tx * 100 + k4];
            ulonglong2 b1 = *(const ulonglong2*)&WST[(tx + 32) * 100 + k4];
            ulonglong2 b2 = *(const ulonglong2*)&WST[(tx + 64) * 100 + k4];
            #pragma unroll
            for (int pp = 0; pp < 8; pp++) {
                ulonglong2 a = *(const ulonglong2*)&featS[(ty * 8 + pp) * 100 + k4];
                acc[pp][0] = fma2(a.x, b0.x, acc[pp][0]);
                acc[pp][0] = fma2(a.y, b0.y, acc[pp][0]);
                acc[pp][1] = fma2(a.x, b1.x, acc[pp][1]);
                acc[pp][1] = fma2(a.y, b1.y, acc[pp][1]);
                acc[pp][2] = fma2(a.x, b2.x, acc[pp][2]);
                acc[pp][2] = fma2(a.y, b2.y, acc[pp][2]);
            }
        }

        if (m < 2) {
            const float* bb_ = (m == 0) ? bq : bk;
            const float* gg_ = (m == 0) ? gq : gk;
            const float* bt_ = (m == 0) ? betaq : betak;
            float bb[3], sc[3], bt[3];
            #pragma unroll
            for (int cc = 0; cc < 3; cc++) {
                int ch = tx + 32 * cc;
                bb[cc] = bb_[ch];
                sc[cc] = gg_[ch] * RS;
                bt[cc] = bt_[ch];
            }
            #pragma unroll
            for (int pp = 0; pp < 8; pp++) {
                int p = ty * 8 + pp;
                #pragma unroll
                for (int cc = 0; cc < 3; cc++) {
                    float r = hsum2(acc[pp][cc]);
                    float v = fmaf(r + bb[cc], sc[cc], bt[cc]);
                    tmpS[p * 100 + tx + 32 * cc] = fmaxf(v, 0.f);
                }
            }
            __syncthreads();
            float* dst = (m == 0) ? d_qW : d_kW;
            for (int t = tid; t < K1_TILE * G; t += K1_THREADS) {
                int p = t / G, g = t % G;
                int n = n0 + p;
                if (n < NPTS) {
                    u64 s2 = 0ull;
                    #pragma unroll
                    for (int c4 = 0; c4 < C; c4 += 4) {
                        ulonglong2 hv = *(const ulonglong2*)&tmpS[p * 100 + c4];
                        ulonglong2 wv = *(const ulonglong2*)&Ww1T[g * 100 + c4];
                        s2 = fma2(hv.x, wv.x, s2);
                        s2 = fma2(hv.y, wv.y, s2);
                    }
                    dst[(size_t)n * G + g] = hsum2(s2);
                }
            }
        } else {
            float bb[3];
            #pragma unroll
            for (int cc = 0; cc < 3; cc++) bb[cc] = bv[tx + 32 * cc];
            #pragma unroll
            for (int pp = 0; pp < 8; pp++) {
                int p = ty * 8 + pp;
                #pragma unroll
                for (int cc = 0; cc < 3; cc++)
                    tmpS[p * 100 + tx + 32 * cc] = hsum2(acc[pp][cc]) + bb[cc];
            }
            __syncthreads();
            for (int i = tid; i < K1_TILE * 24; i += K1_THREADS) {
                int p = i / 24, cq = (i % 24) * 4;
                int n = n0 + p;
                if (n < NPTS)
                    *(float4*)&d_v[(size_t)n * C + cq] = *(const float4*)&tmpS[p * 100 + cq];
            }
        }
    }
}

// ---------------- k2: persistent per-point attention --------------------------
#define PTS 4
#define K2_THREADS (PTS * C)      // 384
#define K2_TILES (NPTS / PTS)     // 12500
#define K2_GRID 304               // 2 blocks x 152 SMs
#define POD_F 2608
#define K2_SMEM_F (C*100 + G*100 + 68 + PTS*POD_F)   // 20700 floats = 82.8KB
#define K2_SMEM (K2_SMEM_F * 4)

__device__ __forceinline__ void podbar(int pod) {
    asm volatile("bar.sync %0, 96;" :: "r"(pod + 1) : "memory");
}

__global__ __launch_bounds__(K2_THREADS, 2)
void k2_attn(const float* __restrict__ coord,
             const int*   __restrict__ refidx,
             const float* __restrict__ Wp1, const float* __restrict__ bp1,
             const float* __restrict__ gp,  const float* __restrict__ betap,
             const float* __restrict__ bp2,
             const float* __restrict__ bw1, const float* __restrict__ gw,
             const float* __restrict__ betaw,
             const float* __restrict__ Ww2, const float* __restrict__ bw2,
             float* __restrict__ out)
{
    extern __shared__ float sh[];
    float* Wp2T = sh;                  // [co][ci] stride 100
    float* MTs  = sh + C * 100;        // [g][cc] stride 100
    float* cst  = MTs + G * 100;       // Ww2(36) bw2(6) bw1(6) gw(6) betaw(6) bM(6)
    float* podb = cst + 68;

    const int tid = threadIdx.x;
    const int pod = tid / C;
    const int c   = tid % C;

    float* P    = podb + pod * POD_F;
    float* hs   = P;            // [16][100]
    float* Hs   = P + 1600;     // [6][100]
    float* ws   = P + 2200;     // [16][8]
    float* us   = P + 2328;     // [16][6]
    float* wls  = P + 2424;     // [16][6]
    float* pos  = P + 2520;     // [16][4]
    float* wsum = P + 2584;     // [8]
    int*   js   = (int*)(P + 2592);  // [16]

    const float RS = rsqrtf(1.0f + 1e-5f);

    // ---- one-time staging ----
    for (int i = tid; i < C * 24; i += K2_THREADS) {
        int co = i / 24, ciq = (i % 24) * 4;
        *(float4*)&Wp2T[co * 100 + ciq] = *(const float4*)&d_Wp2T[co * C + ciq];
    }
    for (int i = tid; i < G * C; i += K2_THREADS)
        MTs[(i / C) * 100 + (i % C)] = d_MT[i];
    if      (tid < 36) cst[tid] = Ww2[tid];
    else if (tid < 42) cst[tid] = bw2[tid - 36];
    else if (tid < 48) cst[tid] = bw1[tid - 42];
    else if (tid < 54) cst[tid] = gw[tid - 48];
    else if (tid < 60) cst[tid] = betaw[tid - 54];
    else if (tid < 66) cst[tid] = d_bM[tid - 60];
    if (c < S) { ws[c * 8 + 6] = 0.f; ws[c * 8 + 7] = 0.f; }   // pads, zero once

    // per-channel params (invariant across points) -> registers, once
    const float w10  = __ldg(&Wp1[c]);
    const float w11  = __ldg(&Wp1[C + c]);
    const float w12  = __ldg(&Wp1[2 * C + c]);
    const float bp1c = __ldg(&bp1[c]);
    const float sp   = __ldg(&gp[c]) * RS;
    const float btp  = __ldg(&betap[c]);
    const float bp2c = __ldg(&bp2[c]);
    const int   gc   = c >> 4;
    __syncthreads();

    // ---- persistent tile loop: pods run independently ----
    for (int t = blockIdx.x; t < K2_TILES; t += K2_GRID) {
        const int n = t * PTS + pod;

        // P1/P2: indices + relative positions
        if (c < S) js[c] = refidx[(size_t)n * S + c];
        if (c < 48) {
            int s = c / 3, d = c % 3;
            int j = __ldg(&refidx[(size_t)n * S + s]);
            pos[s * 4 + d] = __ldg(&coord[(size_t)j * 3 + d]) - __ldg(&coord[(size_t)n * 3 + d]);
        }
        podbar(pod);

        // P3: h[s][c] = relu(bn(pos@Wp1 + bp1)); keep in regs AND smem
        float hr[16];
        #pragma unroll
        for (int s = 0; s < 16; s++) {
            float px = pos[s * 4], py = pos[s * 4 + 1], pz = pos[s * 4 + 2];
            float hv = fmaf(px, w10, fmaf(py, w11, fmaf(pz, w12, bp1c)));
            hv = fmaxf(fmaf(hv, sp, btp), 0.0f);
            hr[s] = hv;
            hs[s * 100 + c] = hv;
        }
        podbar(pod);

        // P4: u[s][g] = relu(bn(kW[j]-qW[n] + h@M + bM + bw1))
        {
            int s = c / 6, g = c % 6;
            u64 a2 = 0ull;
            #pragma unroll
            for (int c4 = 0; c4 < C; c4 += 4) {
                ulonglong2 hv = *(const ulonglong2*)&hs[s * 100 + c4];
                ulonglong2 mv = *(const ulonglong2*)&MTs[g * 100 + c4];
                a2 = fma2(hv.x, mv.x, a2);
                a2 = fma2(hv.y, mv.y, a2);
            }
            float kq = __ldg(&d_kW[(size_t)js[s] * G + g]) - __ldg(&d_qW[(size_t)n * G + g]);
            float tt = kq + hsum2(a2) + cst[60 + g] + cst[42 + g];
            us[s * 6 + g] = fmaxf(fmaf(tt, cst[48 + g] * RS, cst[54 + g]), 0.0f);
        }
        podbar(pod);

        // P5: logits = u @ Ww2 + bw2
        {
            int s = c / 6, g2 = c % 6;
            float lg = cst[36 + g2];
            #pragma unroll
            for (int g = 0; g < 6; g++) lg = fmaf(us[s * 6 + g], cst[g * 6 + g2], lg);
            wls[s * 6 + g2] = lg;
        }
        podbar(pod);

        // P6: softmax over s per g (6 threads/pod)
        if (c < 6) {
            int g = c;
            float m = -1e30f;
            #pragma unroll
            for (int s = 0; s < 16; s++) m = fmaxf(m, wls[s * 6 + g]);
            float sum = 0.f;
            #pragma unroll
            for (int s = 0; s < 16; s++) sum += __expf(wls[s * 6 + g] - m);
            float inv = 1.0f / sum;
            float accw = 0.f;
            #pragma unroll
            for (int s = 0; s < 16; s++) {
                int jp1 = js[s] + 1;
                float msk = (float)((jp1 > 0) - (jp1 < 0));
                float w = __expf(wls[s * 6 + g] - m) * inv * msk;
                ws[s * 8 + g] = w;
                accw += w;
            }
            wsum[g] = accw;
        }
        podbar(pod);

        // P7: H[g][c] = sum_s w[s][g]*hr[s]; vsum = sum_s w[s][gc]*v[j_s][c]
        float Hg[6] = {0, 0, 0, 0, 0, 0};
        float vsum = 0.f;
        #pragma unroll
        for (int s = 0; s < 16; s++) {
            float4 wa = *(const float4*)&ws[s * 8];
            float4 wb = *(const float4*)&ws[s * 8 + 4];
            float h = hr[s];
            Hg[0] = fmaf(wa.x, h, Hg[0]);
            Hg[1] = fmaf(wa.y, h, Hg[1]);
            Hg[2] = fmaf(wa.z, h, Hg[2]);
            Hg[3] = fmaf(wa.w, h, Hg[3]);
            Hg[4] = fmaf(wb.x, h, Hg[4]);
            Hg[5] = fmaf(wb.y, h, Hg[5]);
            float wg = ws[s * 8 + gc];
            vsum = fmaf(wg, __ldg(&d_v[(size_t)js[s] * C + c]), vsum);
        }
        #pragma unroll
        for (int g = 0; g < 6; g++) Hs[g * 100 + c] = Hg[g];
        podbar(pod);

        // P8: out[c] = vsum + bp2[c]*wsum[gc] + H[gc] . Wp2[:,c]
        float accs = fmaf(bp2c, wsum[gc], vsum);
        u64 a2 = 0ull;
        #pragma unroll
        for (int c4 = 0; c4 < C; c4 += 4) {
            ulonglong2 hh = *(const ulonglong2*)&Hs[gc * 100 + c4];
            ulonglong2 wv = *(const ulonglong2*)&Wp2T[c * 100 + c4];
            a2 = fma2(hh.x, wv.x, a2);
            a2 = fma2(hh.y, wv.y, a2);
        }
        out[(size_t)n * C + c] = accs + hsum2(a2);
        podbar(pod);   // protect js/pos/ws/Hs before next tile's writes
    }
}

// ---------------- host launcher ---------------------------------------------
extern "C" void kernel_launch(void* const* d_in, const int* in_sizes, int n_in,
                              void* d_out, int out_size)
{
    bool dict = (in_sizes[2] == NPTS * S);

    const float* feat  = (const float*)d_in[0];
    const float* coord = (const float*)d_in[1];
    const int*   ref   = (const int*)d_in[dict ? 2 : 24];
    int wb = dict ? 3 : 2;
    const float* Wq    = (const float*)d_in[wb + 0];
    const float* bq    = (const float*)d_in[wb + 1];
    const float* gq    = (const float*)d_in[wb + 2];
    const float* betaq = (const float*)d_in[wb + 3];
    const float* Wk    = (const float*)d_in[wb + 4];
    const float* bk    = (const float*)d_in[wb + 5];
    const float* gk    = (const float*)d_in[wb + 6];
    const float* betak = (const float*)d_in[wb + 7];
    const float* Wv    = (const float*)d_in[wb + 8];
    const float* bv    = (const float*)d_in[wb + 9];
    const float* Wp1   = (const float*)d_in[wb + 10];
    const float* bp1   = (const float*)d_in[wb + 11];
    const float* gp    = (const float*)d_in[wb + 12];
    const float* betap = (const float*)d_in[wb + 13];
    const float* Wp2   = (const float*)d_in[wb + 14];
    const float* bp2   = (const float*)d_in[wb + 15];
    const float* Ww1   = (const float*)d_in[wb + 16];
    const float* bw1   = (const float*)d_in[wb + 17];
    const float* gw    = (const float*)d_in[wb + 18];
    const float* betaw = (const float*)d_in[wb + 19];
    const float* Ww2   = (const float*)d_in[wb + 20];
    const float* bw2   = (const float*)d_in[wb + 21];
    float* out = (float*)d_out;

    cudaFuncSetAttribute(k1_qkv,  cudaFuncAttributeMaxDynamicSharedMemorySize, K1_SMEM);
    cudaFuncSetAttribute(k2_attn, cudaFuncAttributeMaxDynamicSharedMemorySize, K2_SMEM);

    int k1_blocks = (NPTS + K1_TILE - 1) / K1_TILE + 1;
    k1_qkv<<<k1_blocks, K1_THREADS, K1_SMEM>>>(
        feat, Wq, bq, gq, betaq, Wk, bk, gk, betak, Wv, bv, Ww1, Wp2, bp2);
    k2_attn<<<K2_GRID, K2_THREADS, K2_SMEM>>>(
        coord, ref, Wp1, bp1, gp, betap, bp2, bw1, gw, betaw, Ww2, bw2, out);
}